// round 16
// baseline (speedup 1.0000x reference)
#include <cuda_runtime.h>
#include <cuda_bf16.h>

// ---------------------------------------------------------------------------
// PointerNet additive attention, B=4, Te=Td=512, E=256, D+E=512, H=64.
// out[b,d,t] = softmax_t( sum_h w2[h]*tanh(dec_t[b,d,h] + ctx_t[b,t,h]) )
// (b2 cancels in softmax.)
//
// SINGLE LAUNCH, block-level pipeline (1064 blocks x 512 threads):
//   bids [0,256):    A ctx blocks, 8 rows, K=256     -> g_ctxT + flag_ctx[j]
//   bids [256,512):  A dec-lo blocks, 8 rows, e 0..255  -> g_decS0 + flag_lo[j]
//   bids [512,768):  A dec-hi blocks, 8 rows, e 256..511-> g_decS1 + flag_hi[j]
//   bids [768,1064): B blocks = the gold 21.3us tanh/softmax loop, with
//                    per-thread acquire-waits on exactly the flags they need.
// A-bids precede B-bids and A never waits => deadlock-free; B blocks start
// their MUFU work as soon as their specific producers land => A's FMA work
// overlaps B's MUFU phase instead of serializing in front of it.
// Flags are monotonic generation counters (safe across CUDA-graph replays).
// ---------------------------------------------------------------------------

#define LOG2E 1.4426950408889634f

typedef unsigned long long ull;

// scratch (device globals: allocation-free)
__device__ float    g_ctxT[4 * 64 * 512];    // [b][h][t]
__device__ float    g_decS0[4 * 512 * 64];   // dec proj, e 0..255 (+bias)
__device__ float    g_decS1[4 * 512 * 64];   // dec proj, e 256..511
__device__ unsigned g_flag_ctx[256];         // ctx 8-row block j done-count
__device__ unsigned g_flag_lo[256];
__device__ unsigned g_flag_hi[256];
__device__ unsigned g_bstart;                // B-block start tickets

// ---- packed f32x2 helpers ----
__device__ __forceinline__ ull pack2(float v) {
    ull r; asm("mov.b64 %0, {%1, %1};" : "=l"(r) : "f"(v)); return r;
}
__device__ __forceinline__ void fma2(ull& d, ull a, ull b) {
    asm("fma.rn.f32x2 %0, %1, %2, %0;" : "+l"(d) : "l"(a), "l"(b));
}
__device__ __forceinline__ void add2(ull& d, ull a) {
    asm("add.rn.f32x2 %0, %0, %1;" : "+l"(d) : "l"(a));
}
__device__ __forceinline__ float ex2_approx(float x) {
    float y; asm("ex2.approx.f32 %0, %1;" : "=f"(y) : "f"(x)); return y;
}
__device__ __forceinline__ float tanh_approx(float x) {
    float y; asm("tanh.approx.f32 %0, %1;" : "=f"(y) : "f"(x)); return y;
}
__device__ __forceinline__ unsigned ld_acquire(const unsigned* p) {
    unsigned v;
    asm volatile("ld.acquire.gpu.global.u32 %0, [%1];" : "=r"(v) : "l"(p) : "memory");
    return v;
}
__device__ __forceinline__ void red_release_add(unsigned* p, unsigned v) {
    asm volatile("red.release.gpu.global.add.u32 [%0], %1;" :: "l"(p), "r"(v) : "memory");
}

__global__ __launch_bounds__(512) void fused_pipeline(
    const float* __restrict__ ctx,   // [4,512,256]
    const float* __restrict__ dec,   // [4,512,512]
    const float* __restrict__ W1i,   // [256,64]
    const float* __restrict__ b1i,   // [64]
    const float* __restrict__ W1h,   // [512,64]
    const float* __restrict__ b1h,   // [64]
    const float* __restrict__ w2,    // [64]
    float* __restrict__ out)         // [4,512,512]
{
    __shared__ __align__(16) float smem[8192];   // 32KB (A tile/partials; B slices)
    __shared__ unsigned gen_sh;

    const int tid  = threadIdx.x;
    const int wid  = tid >> 5;
    const int lane = tid & 31;
    const int bi   = blockIdx.x;

    if (bi < 768) {
        // =========================== A ROLE ================================
        // 8 rows x 256-e x 64-h projection unit. 16 warps x 2 half-warps =
        // 32 e-subranges of 8; lane owns an h-quad (2 packed f32x2 accs).
        const int mode = bi >> 8;                 // 0 ctx, 1 dec-lo, 2 dec-hi
        const int j    = bi & 255;                // 8-row block index (global)
        const int r0   = j << 3;
        const float* X = (mode == 0) ? ctx : (dec + (mode == 2 ? 256 : 0));
        const float* W = (mode == 0) ? W1i : (W1h + (mode == 2 ? 256 * 64 : 0));
        const int xs4  = (mode == 0) ? 64 : 128;  // row stride in float4

        // ---- tile load: 8 rows x 64 float4 = 512 float4 (1 per thread) ----
        {
            const float4* src = reinterpret_cast<const float4*>(X);
            const int r = tid >> 6, c = tid & 63;
            reinterpret_cast<float4*>(smem)[tid] =
                src[(size_t)(r0 + r) * xs4 + c];
        }
        __syncthreads();

        // ---- mainloop: packed dual-fp32 FMA ----
        ull acc[8][2];
        #pragma unroll
        for (int r = 0; r < 8; r++) { acc[r][0] = 0ull; acc[r][1] = 0ull; }

        const int hl   = (lane & 15) << 2;        // h-quad base
        const int half = lane >> 4;
        const int e0   = ((wid << 1) + half) << 3;   // 32 subranges of 8 e
        const float* wptr = W + (size_t)e0 * 64 + hl;

        #pragma unroll
        for (int ec = 0; ec < 8; ec += 4) {
            ulonglong2 w0 = *reinterpret_cast<const ulonglong2*>(wptr + (ec + 0) * 64);
            ulonglong2 w1 = *reinterpret_cast<const ulonglong2*>(wptr + (ec + 1) * 64);
            ulonglong2 w2v = *reinterpret_cast<const ulonglong2*>(wptr + (ec + 2) * 64);
            ulonglong2 w3 = *reinterpret_cast<const ulonglong2*>(wptr + (ec + 3) * 64);
            #pragma unroll
            for (int r = 0; r < 8; r++) {
                float4 x = *reinterpret_cast<const float4*>(&smem[r * 256 + e0 + ec]);
                ull xx;
                xx = pack2(x.x); fma2(acc[r][0], xx, w0.x); fma2(acc[r][1], xx, w0.y);
                xx = pack2(x.y); fma2(acc[r][0], xx, w1.x); fma2(acc[r][1], xx, w1.y);
                xx = pack2(x.z); fma2(acc[r][0], xx, w2v.x); fma2(acc[r][1], xx, w2v.y);
                xx = pack2(x.w); fma2(acc[r][0], xx, w3.x); fma2(acc[r][1], xx, w3.y);
            }
        }

        // combine half-warps (same h-quad, adjacent e-subranges)
        #pragma unroll
        for (int r = 0; r < 8; r++) {
            ull o0 = __shfl_xor_sync(0xffffffffu, acc[r][0], 16);
            ull o1 = __shfl_xor_sync(0xffffffffu, acc[r][1], 16);
            add2(acc[r][0], o0);
            add2(acc[r][1], o1);
        }

        __syncthreads();                          // tile no longer needed
        if (half == 0) {
            #pragma unroll
            for (int r = 0; r < 8; r++)
                *reinterpret_cast<ulonglong2*>(&smem[wid * 512 + r * 64 + hl]) =
                    make_ulonglong2(acc[r][0], acc[r][1]);
        }
        __syncthreads();

        // ---- reduce 16 warp partials; 128 threads own 4 outputs each ----
        if (tid < 128) {
            const int o = tid * 4;                // o = r*64 + h
            const int r = o >> 6;
            const int h = o & 63;
            float4 s = make_float4(0.f, 0.f, 0.f, 0.f);
            #pragma unroll
            for (int w = 0; w < 16; w++) {
                float4 p = *reinterpret_cast<const float4*>(&smem[w * 512 + o]);
                s.x += p.x; s.y += p.y; s.z += p.z; s.w += p.w;
            }

            const int row = r0 + r;               // global row 0..2047
            if (mode == 0) {
                float4 bv = *reinterpret_cast<const float4*>(b1i + h);
                s.x += bv.x; s.y += bv.y; s.z += bv.z; s.w += bv.w;
                const int b = row >> 9, t = row & 511;
                float* dst = g_ctxT + ((size_t)(b << 6)) * 512 + t;
                dst[(h + 0) * 512] = s.x;
                dst[(h + 1) * 512] = s.y;
                dst[(h + 2) * 512] = s.z;
                dst[(h + 3) * 512] = s.w;
            } else if (mode == 1) {
                float4 bv = *reinterpret_cast<const float4*>(b1h + h);
                s.x += bv.x; s.y += bv.y; s.z += bv.z; s.w += bv.w;
                *reinterpret_cast<float4*>(&g_decS0[(size_t)row * 64 + h]) = s;
            } else {
                *reinterpret_cast<float4*>(&g_decS1[(size_t)row * 64 + h]) = s;
            }
        }
        __syncthreads();
        // release: CTA's stores happen-before (bar.sync + release cumulativity)
        if (tid == 0) {
            unsigned* f = (mode == 0) ? &g_flag_ctx[j]
                        : (mode == 1) ? &g_flag_lo[j] : &g_flag_hi[j];
            red_release_add(f, 1u);
        }
    } else {
        // =========================== B ROLE ================================
        const int bb = bi - 768;
        const int b  = bb / 74;
        const int ti = bb % 74;
        const int d0 = ti * 7;

        float* dec_sh = smem;                     // [448]
        float* w2_sh  = smem + 448;               // [64]
        float* red    = smem + 512;               // [112]
        float* inv_sh = smem + 624;               // [7]

        if (tid == 0) gen_sh = atomicAdd(&g_bstart, 1u) / 296u;
        __syncthreads();
        const unsigned target = gen_sh + 1u;

        // prologue: wait dec producers + fill dec tile; w2 in parallel
        if (tid < 448) {
            const int r = tid >> 6;
            if (d0 + r < 512) {
                const int g = (b << 9) + d0 + r;  // global dec row
                const int jd = g >> 3;
                while (ld_acquire(&g_flag_lo[jd]) < target) {}
                while (ld_acquire(&g_flag_hi[jd]) < target) {}
                const size_t idx = (size_t)g * 64 + (tid & 63);
                dec_sh[tid] = g_decS0[idx] + g_decS1[idx];
            } else {
                dec_sh[tid] = 0.f;
            }
        } else {
            w2_sh[tid - 448] = w2[tid - 448] * LOG2E;
        }
        // wait ctx producer for THIS thread's column t = tid
        {
            const int jc = (b << 6) + (tid >> 3);
            while (ld_acquire(&g_flag_ctx[jc]) < target) {}
        }
        __syncthreads();

        // ---- gold tanh-score loop (R13, measured at MUFU floor) ----
        const float* cptr = g_ctxT + (size_t)(b << 6) * 512 + tid;

        float acc[7];
        #pragma unroll
        for (int d = 0; d < 7; d++) acc[d] = 0.f;

        float c0 = cptr[0 * 512];
        float c1 = cptr[1 * 512];
        float c2 = cptr[2 * 512];
        float c3 = cptr[3 * 512];

        #pragma unroll 1
        for (int h = 0; h < 64; h += 4) {
            const int hn = (h + 4) & 63;          // wrap on last iter (unused)
            float n0 = cptr[(hn + 0) * 512];
            float n1 = cptr[(hn + 1) * 512];
            float n2 = cptr[(hn + 2) * 512];
            float n3 = cptr[(hn + 3) * 512];

            float4 w4 = *reinterpret_cast<const float4*>(&w2_sh[h]);
            #pragma unroll
            for (int d = 0; d < 7; d++) {
                float4 dv = *reinterpret_cast<const float4*>(&dec_sh[(d << 6) + h]);
                acc[d] = fmaf(w4.x, tanh_approx(dv.x + c0), acc[d]);
                acc[d] = fmaf(w4.y, tanh_approx(dv.y + c1), acc[d]);
                acc[d] = fmaf(w4.z, tanh_approx(dv.z + c2), acc[d]);
                acc[d] = fmaf(w4.w, tanh_approx(dv.w + c3), acc[d]);
            }
            c0 = n0; c1 = n1; c2 = n2; c3 = n3;
        }

        // softmax over t (acc in log2 domain; b2 cancels; scores bounded by
        // sum|w2|*log2e ~ 9 => no max-shift needed)
        float ex[7];
        #pragma unroll
        for (int d = 0; d < 7; d++) {
            float e = ex2_approx(acc[d]);
            ex[d] = e;
            float s = e;
            #pragma unroll
            for (int off = 16; off; off >>= 1)
                s += __shfl_xor_sync(0xffffffffu, s, off);
            if (lane == 0) red[d * 16 + wid] = s;
        }
        __syncthreads();
        if (wid < 7) {
            float v = (lane < 16) ? red[wid * 16 + lane] : 0.f;
            #pragma unroll
            for (int off = 8; off; off >>= 1)
                v += __shfl_xor_sync(0xffffffffu, v, off);
            if (lane == 0) inv_sh[wid] = 1.0f / v;
        }
        __syncthreads();
        #pragma unroll
        for (int d = 0; d < 7; d++) {
            if (d0 + d < 512)
                out[((size_t)(b << 9) + d0 + d) * 512 + tid] = ex[d] * inv_sh[d];
        }
    }
}

// ---------------------------------------------------------------------------
extern "C" void kernel_launch(void* const* d_in, const int* in_sizes, int n_in,
                              void* d_out, int out_size)
{
    const float* ctx  = (const float*)d_in[0];
    const float* dec  = (const float*)d_in[1];
    const float* W1i  = (const float*)d_in[2];
    const float* b1i  = (const float*)d_in[3];
    const float* W1h  = (const float*)d_in[4];
    const float* b1h  = (const float*)d_in[5];
    const float* w2   = (const float*)d_in[6];
    float* out = (float*)d_out;

    fused_pipeline<<<1064, 512>>>(ctx, dec, W1i, b1i, W1h, b1h, w2, out);
}

// round 17
// speedup vs baseline: 1.2523x; 1.2523x over previous
#include <cuda_runtime.h>
#include <cuda_bf16.h>

// ---------------------------------------------------------------------------
// PointerNet additive attention, B=4, Te=Td=512, E=256, D+E=512, H=64.
// out[b,d,t] = softmax_t( sum_h w2[h]*tanh(dec_t[b,d,h] + ctx_t[b,t,h]) )
// (b2 cancels in softmax.)
//
// SINGLE LAUNCH, block-level pipeline (1064 blocks x 512 threads),
// __launch_bounds__(512, 2): 2 blocks/SM co-residency is THE load-bearing
// constraint (R16 compiled to 70 regs -> 1 block/SM -> 7 waves -> 39us).
//   bids [0,256):    A ctx blocks, 8 rows, K=256       -> g_ctxT + flag_ctx[j]
//   bids [256,512):  A dec-lo blocks, 8 rows, e<256    -> g_decS0 + flag_lo[j]
//   bids [512,768):  A dec-hi blocks, 8 rows, e>=256   -> g_decS1 + flag_hi[j]
//   bids [768,1064): B blocks = gold 21.3us tanh/softmax loop, per-thread
//                    acquire-waits on exactly the producer flags they need.
// A-bids precede B-bids and A never waits => deadlock-free. Flags are
// monotonic generation counters (safe across CUDA-graph replays).
// ---------------------------------------------------------------------------

#define LOG2E 1.4426950408889634f

typedef unsigned long long ull;

// scratch (device globals: allocation-free)
__device__ float    g_ctxT[4 * 64 * 512];    // [b][h][t]
__device__ float    g_decS0[4 * 512 * 64];   // dec proj, e 0..255 (+bias)
__device__ float    g_decS1[4 * 512 * 64];   // dec proj, e 256..511
__device__ unsigned g_flag_ctx[256];         // ctx 8-row block j done-count
__device__ unsigned g_flag_lo[256];
__device__ unsigned g_flag_hi[256];
__device__ unsigned g_bstart;                // B-block start tickets

// ---- packed f32x2 helpers ----
__device__ __forceinline__ ull pack2(float v) {
    ull r; asm("mov.b64 %0, {%1, %1};" : "=l"(r) : "f"(v)); return r;
}
__device__ __forceinline__ void fma2(ull& d, ull a, ull b) {
    asm("fma.rn.f32x2 %0, %1, %2, %0;" : "+l"(d) : "l"(a), "l"(b));
}
__device__ __forceinline__ void add2(ull& d, ull a) {
    asm("add.rn.f32x2 %0, %0, %1;" : "+l"(d) : "l"(a));
}
__device__ __forceinline__ float ex2_approx(float x) {
    float y; asm("ex2.approx.f32 %0, %1;" : "=f"(y) : "f"(x)); return y;
}
__device__ __forceinline__ float tanh_approx(float x) {
    float y; asm("tanh.approx.f32 %0, %1;" : "=f"(y) : "f"(x)); return y;
}
__device__ __forceinline__ unsigned ld_acquire(const unsigned* p) {
    unsigned v;
    asm volatile("ld.acquire.gpu.global.u32 %0, [%1];" : "=r"(v) : "l"(p) : "memory");
    return v;
}
__device__ __forceinline__ void red_release_add(unsigned* p, unsigned v) {
    asm volatile("red.release.gpu.global.add.u32 [%0], %1;" :: "l"(p), "r"(v) : "memory");
}

__global__ void __launch_bounds__(512, 2) fused_pipeline(
    const float* __restrict__ ctx,   // [4,512,256]
    const float* __restrict__ dec,   // [4,512,512]
    const float* __restrict__ W1i,   // [256,64]
    const float* __restrict__ b1i,   // [64]
    const float* __restrict__ W1h,   // [512,64]
    const float* __restrict__ b1h,   // [64]
    const float* __restrict__ w2,    // [64]
    float* __restrict__ out)         // [4,512,512]
{
    __shared__ __align__(16) float smem[8192];   // 32KB (A tile/partials; B slices)
    __shared__ unsigned gen_sh;

    const int tid  = threadIdx.x;
    const int wid  = tid >> 5;
    const int lane = tid & 31;
    const int bi   = blockIdx.x;

    if (bi < 768) {
        // =========================== A ROLE ================================
        // 8 rows x 256-e x 64-h projection unit. 16 warps x 2 half-warps =
        // 32 e-subranges of 8; lane owns an h-quad (2 packed f32x2 accs).
        const int mode = bi >> 8;                 // 0 ctx, 1 dec-lo, 2 dec-hi
        const int j    = bi & 255;                // 8-row block index (global)
        const int r0   = j << 3;
        const float* X = (mode == 0) ? ctx : (dec + (mode == 2 ? 256 : 0));
        const float* W = (mode == 0) ? W1i : (W1h + (mode == 2 ? 256 * 64 : 0));
        const int xs4  = (mode == 0) ? 64 : 128;  // row stride in float4

        // ---- tile load: 8 rows x 64 float4 = 512 float4 (1 per thread) ----
        {
            const float4* src = reinterpret_cast<const float4*>(X);
            const int r = tid >> 6, c = tid & 63;
            reinterpret_cast<float4*>(smem)[tid] =
                src[(size_t)(r0 + r) * xs4 + c];
        }
        __syncthreads();

        // ---- mainloop: packed dual-fp32 FMA, weights in 2 pairs to cap
        //      live registers (<=64 for 2-blocks/SM residency) ----
        ull acc[8][2];
        #pragma unroll
        for (int r = 0; r < 8; r++) { acc[r][0] = 0ull; acc[r][1] = 0ull; }

        const int hl   = (lane & 15) << 2;        // h-quad base
        const int half = lane >> 4;
        const int e0   = ((wid << 1) + half) << 3;   // 32 subranges of 8 e
        const float* wptr = W + (size_t)e0 * 64 + hl;

        #pragma unroll
        for (int ec = 0; ec < 8; ec += 2) {
            ulonglong2 w0 = *reinterpret_cast<const ulonglong2*>(wptr + (ec + 0) * 64);
            ulonglong2 w1 = *reinterpret_cast<const ulonglong2*>(wptr + (ec + 1) * 64);
            #pragma unroll
            for (int r = 0; r < 8; r++) {
                float2 x = *reinterpret_cast<const float2*>(&smem[r * 256 + e0 + ec]);
                ull xx;
                xx = pack2(x.x); fma2(acc[r][0], xx, w0.x); fma2(acc[r][1], xx, w0.y);
                xx = pack2(x.y); fma2(acc[r][0], xx, w1.x); fma2(acc[r][1], xx, w1.y);
            }
        }

        // combine half-warps (same h-quad, adjacent e-subranges)
        #pragma unroll
        for (int r = 0; r < 8; r++) {
            ull o0 = __shfl_xor_sync(0xffffffffu, acc[r][0], 16);
            ull o1 = __shfl_xor_sync(0xffffffffu, acc[r][1], 16);
            add2(acc[r][0], o0);
            add2(acc[r][1], o1);
        }

        __syncthreads();                          // tile no longer needed
        if (half == 0) {
            #pragma unroll
            for (int r = 0; r < 8; r++)
                *reinterpret_cast<ulonglong2*>(&smem[wid * 512 + r * 64 + hl]) =
                    make_ulonglong2(acc[r][0], acc[r][1]);
        }
        __syncthreads();

        // ---- reduce 16 warp partials; 128 threads own 4 outputs each ----
        if (tid < 128) {
            const int o = tid * 4;                // o = r*64 + h
            const int r = o >> 6;
            const int h = o & 63;
            float4 s = make_float4(0.f, 0.f, 0.f, 0.f);
            #pragma unroll
            for (int w = 0; w < 16; w++) {
                float4 p = *reinterpret_cast<const float4*>(&smem[w * 512 + o]);
                s.x += p.x; s.y += p.y; s.z += p.z; s.w += p.w;
            }

            const int row = r0 + r;               // global row 0..2047
            if (mode == 0) {
                float4 bv = *reinterpret_cast<const float4*>(b1i + h);
                s.x += bv.x; s.y += bv.y; s.z += bv.z; s.w += bv.w;
                const int b = row >> 9, t = row & 511;
                float* dst = g_ctxT + ((size_t)(b << 6)) * 512 + t;
                dst[(h + 0) * 512] = s.x;
                dst[(h + 1) * 512] = s.y;
                dst[(h + 2) * 512] = s.z;
                dst[(h + 3) * 512] = s.w;
            } else if (mode == 1) {
                float4 bv = *reinterpret_cast<const float4*>(b1h + h);
                s.x += bv.x; s.y += bv.y; s.z += bv.z; s.w += bv.w;
                *reinterpret_cast<float4*>(&g_decS0[(size_t)row * 64 + h]) = s;
            } else {
                *reinterpret_cast<float4*>(&g_decS1[(size_t)row * 64 + h]) = s;
            }
        }
        __syncthreads();
        // release: CTA's stores happen-before (bar.sync + release cumulativity)
        if (tid == 0) {
            unsigned* f = (mode == 0) ? &g_flag_ctx[j]
                        : (mode == 1) ? &g_flag_lo[j] : &g_flag_hi[j];
            red_release_add(f, 1u);
        }
    } else {
        // =========================== B ROLE ================================
        const int bb = bi - 768;
        const int b  = bb / 74;
        const int ti = bb % 74;
        const int d0 = ti * 7;

        float* dec_sh = smem;                     // [448]
        float* w2_sh  = smem + 448;               // [64]
        float* red    = smem + 512;               // [112]
        float* inv_sh = smem + 624;               // [7]

        if (tid == 0) gen_sh = atomicAdd(&g_bstart, 1u) / 296u;
        __syncthreads();
        const unsigned target = gen_sh + 1u;

        // prologue: wait dec producers + fill dec tile; w2 in parallel
        if (tid < 448) {
            const int r = tid >> 6;
            if (d0 + r < 512) {
                const int g = (b << 9) + d0 + r;  // global dec row
                const int jd = g >> 3;
                while (ld_acquire(&g_flag_lo[jd]) < target) {}
                while (ld_acquire(&g_flag_hi[jd]) < target) {}
                const size_t idx = (size_t)g * 64 + (tid & 63);
                dec_sh[tid] = g_decS0[idx] + g_decS1[idx];
            } else {
                dec_sh[tid] = 0.f;
            }
        } else {
            w2_sh[tid - 448] = w2[tid - 448] * LOG2E;
        }
        // wait ctx producer for THIS thread's column t = tid
        {
            const int jc = (b << 6) + (tid >> 3);
            while (ld_acquire(&g_flag_ctx[jc]) < target) {}
        }
        __syncthreads();

        // ---- gold tanh-score loop (R13, measured at MUFU floor) ----
        const float* cptr = g_ctxT + (size_t)(b << 6) * 512 + tid;

        float acc[7];
        #pragma unroll
        for (int d = 0; d < 7; d++) acc[d] = 0.f;

        float c0 = cptr[0 * 512];
        float c1 = cptr[1 * 512];
        float c2 = cptr[2 * 512];
        float c3 = cptr[3 * 512];

        #pragma unroll 1
        for (int h = 0; h < 64; h += 4) {
            const int hn = (h + 4) & 63;          // wrap on last iter (unused)
            float n0 = cptr[(hn + 0) * 512];
            float n1 = cptr[(hn + 1) * 512];
            float n2 = cptr[(hn + 2) * 512];
            float n3 = cptr[(hn + 3) * 512];

            float4 w4 = *reinterpret_cast<const float4*>(&w2_sh[h]);
            #pragma unroll
            for (int d = 0; d < 7; d++) {
                float4 dv = *reinterpret_cast<const float4*>(&dec_sh[(d << 6) + h]);
                acc[d] = fmaf(w4.x, tanh_approx(dv.x + c0), acc[d]);
                acc[d] = fmaf(w4.y, tanh_approx(dv.y + c1), acc[d]);
                acc[d] = fmaf(w4.z, tanh_approx(dv.z + c2), acc[d]);
                acc[d] = fmaf(w4.w, tanh_approx(dv.w + c3), acc[d]);
            }
            c0 = n0; c1 = n1; c2 = n2; c3 = n3;
        }

        // softmax over t (acc in log2 domain; b2 cancels; scores bounded by
        // sum|w2|*log2e ~ 9 => no max-shift needed)
        float ex[7];
        #pragma unroll
        for (int d = 0; d < 7; d++) {
            float e = ex2_approx(acc[d]);
            ex[d] = e;
            float s = e;
            #pragma unroll
            for (int off = 16; off; off >>= 1)
                s += __shfl_xor_sync(0xffffffffu, s, off);
            if (lane == 0) red[d * 16 + wid] = s;
        }
        __syncthreads();
        if (wid < 7) {
            float v = (lane < 16) ? red[wid * 16 + lane] : 0.f;
            #pragma unroll
            for (int off = 8; off; off >>= 1)
                v += __shfl_xor_sync(0xffffffffu, v, off);
            if (lane == 0) inv_sh[wid] = 1.0f / v;
        }
        __syncthreads();
        #pragma unroll
        for (int d = 0; d < 7; d++) {
            if (d0 + d < 512)
                out[((size_t)(b << 9) + d0 + d) * 512 + tid] = ex[d] * inv_sh[d];
        }
    }
}

// ---------------------------------------------------------------------------
extern "C" void kernel_launch(void* const* d_in, const int* in_sizes, int n_in,
                              void* d_out, int out_size)
{
    const float* ctx  = (const float*)d_in[0];
    const float* dec  = (const float*)d_in[1];
    const float* W1i  = (const float*)d_in[2];
    const float* b1i  = (const float*)d_in[3];
    const float* W1h  = (const float*)d_in[4];
    const float* b1h  = (const float*)d_in[5];
    const float* w2   = (const float*)d_in[6];
    float* out = (float*)d_out;

    fused_pipeline<<<1064, 512>>>(ctx, dec, W1i, b1i, W1h, b1h, w2, out);
}